// round 11
// baseline (speedup 1.0000x reference)
#include <cuda_runtime.h>
#include <math.h>

// Problem dims
#define BB    32
#define TENC  1024
#define ENCD  1024
#define DECD  1024
#define MELD  80
// Attention split
#define NC    32          // chunks over T
#define CT    32          // timesteps per chunk
// LSTM GEMM
#define KTOT  2128        // 80 (mel) + 1024 (ctx) + 1024 (h)
#define KSPLIT 38
#define KSL    56         // K-values per split (38*56 = 2128)

// Output layout: [mel(32*80), h_new(32*1024), c_new(32*1024)]
#define OFF_MEL 0
#define OFF_H   (BB*MELD)
#define OFF_C   (BB*MELD + BB*DECD)

// Scratch (static device memory — no allocations allowed)
__device__ float g_m[BB*NC];
__device__ float g_l[BB*NC];
__device__ float g_acc[BB*NC*ENCD];
__device__ float g_ctx[BB*ENCD];
__device__ float g_zp[KSPLIT*BB*4*DECD];   // ~20 MB

#define LOG2E  1.4426950408889634f
#define LOG2E2 2.8853900817779268f

// HW tanh (MUFU.TANH) — attention scores only; error damped by softmax+GEMM.
__device__ __forceinline__ float tanhA(float x) {
    float y; asm("tanh.approx.f32 %0, %1;" : "=f"(y) : "f"(x)); return y;
}
// Accurate-ish versions for the LSTM gate outputs (written directly to d_out)
__device__ __forceinline__ float fast_tanh(float x) {
    float u = exp2f(x * LOG2E2);
    return 1.0f - __fdividef(2.0f, u + 1.0f);
}
__device__ __forceinline__ float fast_sig(float x) {
    return __fdividef(1.0f, 1.0f + exp2f(-LOG2E * x));
}

// f32x2 packed FMA helpers
typedef unsigned long long u64t;
__device__ __forceinline__ u64t pack2(float w) {
    u64t r; asm("mov.b64 %0, {%1, %1};" : "=l"(r) : "f"(w)); return r;
}
__device__ __forceinline__ void fma2(u64t& a, u64t x, u64t w) {
    asm("fma.rn.f32x2 %0, %1, %2, %0;" : "+l"(a) : "l"(x), "l"(w));
}
__device__ __forceinline__ float2 unpack2(u64t a) {
    float2 f; asm("mov.b64 {%0, %1}, %2;" : "=f"(f.x), "=f"(f.y) : "l"(a)); return f;
}

// Weight row element for global k, column j.
__device__ __forceinline__ const float* wrow_ptr(
    const float* __restrict__ Wk, const float* __restrict__ Wr, int k, int j)
{
    return (k < MELD + ENCD) ? (Wk + (long)k * 4096 + j)
                             : (Wr + (long)(k - MELD - ENCD) * 4096 + j);
}

// ---------------------------------------------------------------------------
// ncu-slot pad kernel: capture (launch index 3) lands on lstm_gemm.
// ---------------------------------------------------------------------------
__global__ void pad_slot_1() {}

// ---------------------------------------------------------------------------
// Kernel A: attention chunk partials. Grid (B, NC), 256 threads (8 warps).
// (Measured 31.7us, DRAM 57% — unchanged.)
// ---------------------------------------------------------------------------
__global__ void __launch_bounds__(256) attn_partial(
    const float* __restrict__ enc, const float* __restrict__ h,
    const float* __restrict__ scale)
{
    const int b = blockIdx.x, c = blockIdx.y;
    const int tid = threadIdx.x;
    const int wid = tid >> 5, lane = tid & 31;

    __shared__ float4 hsm[256];
    __shared__ float s_sm[CT];
    __shared__ float w_sm[CT];

    hsm[tid] = ((const float4*)(h + b*DECD))[tid];

    float4 sc[8];
    const float4* s4 = (const float4*)scale;
    #pragma unroll
    for (int k = 0; k < 8; k++) sc[k] = s4[lane + 32*k];

    __syncthreads();

    const float* encb = enc + ((long)(b*TENC) + c*CT)*ENCD;

    // ---- Phase A ----
    #pragma unroll
    for (int i = 0; i < 4; i++) {
        const int t = wid*4 + i;
        const float4* eA = (const float4*)(encb + t*ENCD) + lane;
        float p0 = 0.f, p1 = 0.f, p2 = 0.f, p3 = 0.f;
        #pragma unroll
        for (int k = 0; k < 8; k++) {
            float4 e  = eA[32*k];
            float4 hv = hsm[lane + 32*k];
            p0 = fmaf(sc[k].x, tanhA(hv.x + e.x), p0);
            p1 = fmaf(sc[k].y, tanhA(hv.y + e.y), p1);
            p2 = fmaf(sc[k].z, tanhA(hv.z + e.z), p2);
            p3 = fmaf(sc[k].w, tanhA(hv.w + e.w), p3);
        }
        float s = (p0 + p1) + (p2 + p3);
        #pragma unroll
        for (int off = 16; off > 0; off >>= 1)
            s += __shfl_xor_sync(0xffffffffu, s, off);
        if (lane == 0) s_sm[t] = s;
    }
    __syncthreads();

    // ---- Merge: chunk-local softmax (warp 0) ----
    if (wid == 0) {
        float s = s_sm[lane];
        float m = s;
        #pragma unroll
        for (int off = 16; off > 0; off >>= 1)
            m = fmaxf(m, __shfl_xor_sync(0xffffffffu, m, off));
        float wv = exp2f((s - m) * LOG2E);
        float l = wv;
        #pragma unroll
        for (int off = 16; off > 0; off >>= 1)
            l += __shfl_xor_sync(0xffffffffu, l, off);
        w_sm[lane] = wv;
        if (lane == 0) { g_m[b*NC + c] = m; g_l[b*NC + c] = l; }
    }
    __syncthreads();

    // ---- Phase B ----
    const float4* eB = (const float4*)encb + wid*32 + lane;
    float4 acc = make_float4(0.f, 0.f, 0.f, 0.f);
    #pragma unroll 8
    for (int t = 0; t < CT; t++) {
        float wv = w_sm[t];
        float4 v = eB[t*256];
        acc.x = fmaf(wv, v.x, acc.x); acc.y = fmaf(wv, v.y, acc.y);
        acc.z = fmaf(wv, v.z, acc.z); acc.w = fmaf(wv, v.w, acc.w);
    }
    ((float4*)(g_acc + (b*NC + c)*ENCD))[wid*32 + lane] = acc;
}

// ---------------------------------------------------------------------------
// Kernel B: combine chunk partials -> context. Grid (B), 256 threads.
// ---------------------------------------------------------------------------
__global__ void __launch_bounds__(256) attn_combine()
{
    const int b = blockIdx.x, tid = threadIdx.x;
    __shared__ float sm[NC], sl[NC], sf[NC];
    if (tid < NC) { sm[tid] = g_m[b*NC + tid]; sl[tid] = g_l[b*NC + tid]; }
    __syncthreads();
    float M = -INFINITY;
    #pragma unroll
    for (int c = 0; c < NC; c++) M = fmaxf(M, sm[c]);
    if (tid < NC) sf[tid] = exp2f((sm[tid] - M) * LOG2E);
    __syncthreads();
    float L = 0.0f;
    #pragma unroll
    for (int c = 0; c < NC; c++) L += sl[c] * sf[c];
    float invL = __fdividef(1.0f, L);

    const float4* ga = (const float4*)g_acc;
    float4 v = make_float4(0.f, 0.f, 0.f, 0.f);
    #pragma unroll 8
    for (int c = 0; c < NC; c++) {
        float4 a = ga[(b*NC + c)*256 + tid];
        float f = sf[c];
        v.x = fmaf(a.x, f, v.x); v.y = fmaf(a.y, f, v.y);
        v.z = fmaf(a.z, f, v.z); v.w = fmaf(a.w, f, v.w);
    }
    v.x *= invL; v.y *= invL; v.z *= invL; v.w *= invL;
    ((float4*)(g_ctx + b*ENCD))[tid] = v;
}

// ---------------------------------------------------------------------------
// Kernel C: z partials. Grid (32 j-blocks, KSPLIT=38), 128 threads.
// Restructured per R10 profile (latency-bound, nothing saturated):
//  - whole 56-K x-slice staged in smem up front (ONE sync, no mainloop barriers)
//  - weight rows double-buffered 4-deep (MLP=4 on the DRAM stream)
//  - x read as LDS.128 broadcast (8 LDS per 16 FFMA2, was 16)
//  - KSPLIT 19->38 doubles resident warps (~33/SM) for latency hiding
// ---------------------------------------------------------------------------
__global__ void __launch_bounds__(128) lstm_gemm(
    const float* __restrict__ pm, const float* __restrict__ h,
    const float* __restrict__ Wk, const float* __restrict__ Wr)
{
    const int tid = threadIdx.x;
    const int j   = blockIdx.x * 128 + tid;
    const int ks  = blockIdx.y;
    const int k0  = ks * KSL;

    __shared__ __align__(16) float xs[KSL][32];   // 7 KB

    // Stage x slice: 56*32 = 1792 = 14*128
    #pragma unroll
    for (int i = 0; i < 14; i++) {
        int idx = tid + 128*i;
        int kl = idx >> 5, b = idx & 31;
        int k  = k0 + kl;
        float v;
        if (k < MELD)            v = pm[b*MELD + k];
        else if (k < MELD+ENCD)  v = g_ctx[b*ENCD + (k - MELD)];
        else                     v = h[b*DECD + (k - MELD - ENCD)];
        xs[kl][b] = v;
    }
    __syncthreads();

    u64t acc2[16];
    #pragma unroll
    for (int i = 0; i < 16; i++) acc2[i] = 0ull;

    float wbuf[4];
    #pragma unroll
    for (int u = 0; u < 4; u++) wbuf[u] = *wrow_ptr(Wk, Wr, k0 + u, j);

    #pragma unroll 2
    for (int g = 0; g < KSL/4; g++) {
        float wnext[4];
        if (g < KSL/4 - 1) {
            #pragma unroll
            for (int u = 0; u < 4; u++)
                wnext[u] = *wrow_ptr(Wk, Wr, k0 + 4*(g+1) + u, j);
        }
        #pragma unroll
        for (int u = 0; u < 4; u++) {
            u64t w2 = pack2(wbuf[u]);
            const ulonglong2* xp = (const ulonglong2*)xs[4*g + u];
            #pragma unroll
            for (int q = 0; q < 8; q++) {
                ulonglong2 x2 = xp[q];       // LDS.128 broadcast: batches 4q..4q+3
                fma2(acc2[2*q],   x2.x, w2);
                fma2(acc2[2*q+1], x2.y, w2);
            }
        }
        #pragma unroll
        for (int u = 0; u < 4; u++) wbuf[u] = wnext[u];
    }

    #pragma unroll
    for (int bb = 0; bb < 16; bb++) {
        float2 f = unpack2(acc2[bb]);
        g_zp[(ks*32 + 2*bb  )*4*DECD + j] = f.x;
        g_zp[(ks*32 + 2*bb+1)*4*DECD + j] = f.y;
    }
}

// ---------------------------------------------------------------------------
// Kernel D: sum K-split partials + bias, gates. Grid 128 x 256 threads.
// ---------------------------------------------------------------------------
__global__ void __launch_bounds__(256) lstm_gates(
    const float* __restrict__ c_in, const float* __restrict__ bias,
    float* __restrict__ out)
{
    const int idx = blockIdx.x*256 + threadIdx.x;   // [0, 32768)
    const int b = idx >> 10, jj = idx & 1023;

    float zi = bias[jj], zf = bias[DECD + jj];
    float zg = bias[2*DECD + jj], zo = bias[3*DECD + jj];
    #pragma unroll
    for (int ks = 0; ks < KSPLIT; ks++) {
        const float* zp = g_zp + (ks*32 + b)*4*DECD;
        zi += zp[jj];
        zf += zp[DECD + jj];
        zg += zp[2*DECD + jj];
        zo += zp[3*DECD + jj];
    }
    float ig = fast_sig(zi), fg = fast_sig(zf), og = fast_sig(zo);
    float gg = fast_tanh(zg);
    float cn = fmaf(fg, c_in[idx], ig * gg);
    float hn = og * fast_tanh(cn);
    out[OFF_H + idx] = hn;
    out[OFF_C + idx] = cn;
}

// ---------------------------------------------------------------------------
// Kernel E: mel projection. Grid (B), block (96, 4).
// ---------------------------------------------------------------------------
__global__ void __launch_bounds__(384) mel_proj(
    const float* __restrict__ pw, const float* __restrict__ pb,
    float* __restrict__ out)
{
    const int b = blockIdx.x;
    const int j = threadIdx.x;          // 0..95 (80 active)
    const int ty = threadIdx.y;         // 0..3
    __shared__ float red[4][96];

    float a0 = 0.f, a1 = 0.f, a2 = 0.f, a3 = 0.f;
    if (j < MELD) {
        const float* hn = out + OFF_H + b*DECD + ty*256;
        const float* pwk = pw + (long)(ty*256)*MELD + j;
        #pragma unroll 4
        for (int k = 0; k < 256; k += 4) {
            a0 = fmaf(hn[k  ], pwk[(k  )*MELD], a0);
            a1 = fmaf(hn[k+1], pwk[(k+1)*MELD], a1);
            a2 = fmaf(hn[k+2], pwk[(k+2)*MELD], a2);
            a3 = fmaf(hn[k+3], pwk[(k+3)*MELD], a3);
        }
    }
    red[ty][j] = (a0 + a1) + (a2 + a3);
    __syncthreads();
    if (ty == 0 && j < MELD) {
        out[OFF_MEL + b*MELD + j] =
            red[0][j] + red[1][j] + red[2][j] + red[3][j] + pb[j];
    }
}

// ---------------------------------------------------------------------------
extern "C" void kernel_launch(void* const* d_in, const int* in_sizes, int n_in,
                              void* d_out, int out_size)
{
    const float* pm    = (const float*)d_in[0];  // prev_mel_frame [32,80]
    const float* enc   = (const float*)d_in[1];  // encoder_outputs [32,1024,1024]
    const float* h     = (const float*)d_in[2];  // h [32,1024]
    const float* c     = (const float*)d_in[3];  // c [32,1024]
    const float* ascl  = (const float*)d_in[4];  // attn_scale [1024]
    const float* Wk    = (const float*)d_in[5];  // kernel [1104,4096]
    const float* Wr    = (const float*)d_in[6];  // rec_kernel [1024,4096]
    const float* bias  = (const float*)d_in[7];  // bias [4096]
    const float* pw    = (const float*)d_in[8];  // proj_w [1024,80]
    const float* pb    = (const float*)d_in[9];  // proj_b [80]
    float* out = (float*)d_out;

    // One pad -> ncu capture slot (launch index 3) stays on lstm_gemm.
    pad_slot_1<<<1, 32>>>();

    dim3 gA(BB, NC);
    attn_partial<<<gA, 256>>>(enc, h, ascl);
    attn_combine<<<BB, 256>>>();
    dim3 gC(32, KSPLIT);
    lstm_gemm<<<gC, 128>>>(pm, h, Wk, Wr);
    lstm_gates<<<128, 256>>>(c, bias, out);
    dim3 bE(96, 4);
    mel_proj<<<BB, bE>>>(pw, pb, out);
}

// round 15
// speedup vs baseline: 1.1055x; 1.1055x over previous
#include <cuda_runtime.h>
#include <math.h>
#include <stdint.h>

// Problem dims
#define BB    32
#define TENC  1024
#define ENCD  1024
#define DECD  1024
#define MELD  80
// Attention split
#define NC    32          // chunks over T
#define CT    32          // timesteps per chunk
// LSTM GEMM (tensor-core)
#define KTOT  2128        // 80 (mel) + 1024 (ctx) + 1024 (h)
#define KSPLIT 7
#define KPER   304        // K per split (7*304 = 2128)
#define CHUNK  16         // k per staged chunk (4 k4-steps)
#define NCHUNK 19         // 19*16 = 304
#define WS_STRIDE 72      // smem stride (conflict-free A frags)
#define XS_STRIDE 40      // smem stride (conflict-free B frags)

// Output layout: [mel(32*80), h_new(32*1024), c_new(32*1024)]
#define OFF_MEL 0
#define OFF_H   (BB*MELD)
#define OFF_C   (BB*MELD + BB*DECD)

// Scratch (static device memory — no allocations allowed)
__device__ float g_m[BB*NC];
__device__ float g_l[BB*NC];
__device__ float g_acc[BB*NC*ENCD];
__device__ float g_xt[KTOT*BB];            // x transposed: [k][b]
__device__ float g_zp[KSPLIT*BB*4*DECD];

#define LOG2E  1.4426950408889634f
#define LOG2E2 2.8853900817779268f

// HW tanh (MUFU.TANH) — attention scores only; error damped by softmax+GEMM.
__device__ __forceinline__ float tanhA(float x) {
    float y; asm("tanh.approx.f32 %0, %1;" : "=f"(y) : "f"(x)); return y;
}
// Accurate-ish versions for the LSTM gate outputs (written directly to d_out)
__device__ __forceinline__ float fast_tanh(float x) {
    float u = exp2f(x * LOG2E2);
    return 1.0f - __fdividef(2.0f, u + 1.0f);
}
__device__ __forceinline__ float fast_sig(float x) {
    return __fdividef(1.0f, 1.0f + exp2f(-LOG2E * x));
}

// tf32 helpers
__device__ __forceinline__ uint32_t cvt_tf32(float f) {
    uint32_t u; asm("cvt.rna.tf32.f32 %0, %1;" : "=r"(u) : "f"(f)); return u;
}
__device__ __forceinline__ void mma_tf32(
    float& d0, float& d1, float& d2, float& d3,
    uint32_t a0, uint32_t a1, uint32_t b0)
{
    asm("mma.sync.aligned.m16n8k4.row.col.f32.tf32.tf32.f32 "
        "{%0,%1,%2,%3},{%4,%5},{%6},{%0,%1,%2,%3};"
        : "+f"(d0), "+f"(d1), "+f"(d2), "+f"(d3)
        : "r"(a0), "r"(a1), "r"(b0));
}

// ---------------------------------------------------------------------------
// Kernel 0: build transposed x for pm and h segments (ctx filled by combine).
// g_xt[k][b], k in [0,80) = pm, [1104,2128) = h. Grid <<<266,256>>> covers all;
// middle segment skipped (owned by attn_combine).
// ---------------------------------------------------------------------------
__global__ void prep_xt(const float* __restrict__ pm, const float* __restrict__ h)
{
    int idx = blockIdx.x*256 + threadIdx.x;    // [0, 68096)
    if (idx >= KTOT*BB) return;
    int k = idx >> 5, b = idx & 31;
    if (k < MELD)            g_xt[idx] = pm[b*MELD + k];
    else if (k >= MELD+ENCD) g_xt[idx] = h[b*DECD + (k - MELD - ENCD)];
}

// ---------------------------------------------------------------------------
// Kernel A: attention chunk partials. Grid (B, NC), 256 threads (8 warps).
// (Measured 31.7us, DRAM 57% — unchanged.)
// ---------------------------------------------------------------------------
__global__ void __launch_bounds__(256) attn_partial(
    const float* __restrict__ enc, const float* __restrict__ h,
    const float* __restrict__ scale)
{
    const int b = blockIdx.x, c = blockIdx.y;
    const int tid = threadIdx.x;
    const int wid = tid >> 5, lane = tid & 31;

    __shared__ float4 hsm[256];
    __shared__ float s_sm[CT];
    __shared__ float w_sm[CT];

    hsm[tid] = ((const float4*)(h + b*DECD))[tid];

    float4 sc[8];
    const float4* s4 = (const float4*)scale;
    #pragma unroll
    for (int k = 0; k < 8; k++) sc[k] = s4[lane + 32*k];

    __syncthreads();

    const float* encb = enc + ((long)(b*TENC) + c*CT)*ENCD;

    // ---- Phase A ----
    #pragma unroll
    for (int i = 0; i < 4; i++) {
        const int t = wid*4 + i;
        const float4* eA = (const float4*)(encb + t*ENCD) + lane;
        float p0 = 0.f, p1 = 0.f, p2 = 0.f, p3 = 0.f;
        #pragma unroll
        for (int k = 0; k < 8; k++) {
            float4 e  = eA[32*k];
            float4 hv = hsm[lane + 32*k];
            p0 = fmaf(sc[k].x, tanhA(hv.x + e.x), p0);
            p1 = fmaf(sc[k].y, tanhA(hv.y + e.y), p1);
            p2 = fmaf(sc[k].z, tanhA(hv.z + e.z), p2);
            p3 = fmaf(sc[k].w, tanhA(hv.w + e.w), p3);
        }
        float s = (p0 + p1) + (p2 + p3);
        #pragma unroll
        for (int off = 16; off > 0; off >>= 1)
            s += __shfl_xor_sync(0xffffffffu, s, off);
        if (lane == 0) s_sm[t] = s;
    }
    __syncthreads();

    // ---- Merge: chunk-local softmax (warp 0) ----
    if (wid == 0) {
        float s = s_sm[lane];
        float m = s;
        #pragma unroll
        for (int off = 16; off > 0; off >>= 1)
            m = fmaxf(m, __shfl_xor_sync(0xffffffffu, m, off));
        float wv = exp2f((s - m) * LOG2E);
        float l = wv;
        #pragma unroll
        for (int off = 16; off > 0; off >>= 1)
            l += __shfl_xor_sync(0xffffffffu, l, off);
        w_sm[lane] = wv;
        if (lane == 0) { g_m[b*NC + c] = m; g_l[b*NC + c] = l; }
    }
    __syncthreads();

    // ---- Phase B ----
    const float4* eB = (const float4*)encb + wid*32 + lane;
    float4 acc = make_float4(0.f, 0.f, 0.f, 0.f);
    #pragma unroll 8
    for (int t = 0; t < CT; t++) {
        float wv = w_sm[t];
        float4 v = eB[t*256];
        acc.x = fmaf(wv, v.x, acc.x); acc.y = fmaf(wv, v.y, acc.y);
        acc.z = fmaf(wv, v.z, acc.z); acc.w = fmaf(wv, v.w, acc.w);
    }
    ((float4*)(g_acc + (b*NC + c)*ENCD))[wid*32 + lane] = acc;
}

// ---------------------------------------------------------------------------
// Kernel B: combine chunk partials -> context, written TRANSPOSED into g_xt
// at rows [MELD, MELD+ENCD). Grid (B), 256 threads.
// ---------------------------------------------------------------------------
__global__ void __launch_bounds__(256) attn_combine()
{
    const int b = blockIdx.x, tid = threadIdx.x;
    __shared__ float sm[NC], sl[NC], sf[NC];
    if (tid < NC) { sm[tid] = g_m[b*NC + tid]; sl[tid] = g_l[b*NC + tid]; }
    __syncthreads();
    float M = -INFINITY;
    #pragma unroll
    for (int c = 0; c < NC; c++) M = fmaxf(M, sm[c]);
    if (tid < NC) sf[tid] = exp2f((sm[tid] - M) * LOG2E);
    __syncthreads();
    float L = 0.0f;
    #pragma unroll
    for (int c = 0; c < NC; c++) L += sl[c] * sf[c];
    float invL = __fdividef(1.0f, L);

    const float4* ga = (const float4*)g_acc;
    float4 v = make_float4(0.f, 0.f, 0.f, 0.f);
    #pragma unroll 8
    for (int c = 0; c < NC; c++) {
        float4 a = ga[(b*NC + c)*256 + tid];
        float f = sf[c];
        v.x = fmaf(a.x, f, v.x); v.y = fmaf(a.y, f, v.y);
        v.z = fmaf(a.z, f, v.z); v.w = fmaf(a.w, f, v.w);
    }
    v.x *= invL; v.y *= invL; v.z *= invL; v.w *= invL;
    // transposed store: g_xt[(MELD + d)*32 + b]
    const int d0 = tid*4;
    g_xt[(MELD + d0    )*32 + b] = v.x;
    g_xt[(MELD + d0 + 1)*32 + b] = v.y;
    g_xt[(MELD + d0 + 2)*32 + b] = v.z;
    g_xt[(MELD + d0 + 3)*32 + b] = v.w;
}

// ---------------------------------------------------------------------------
// Kernel C: z partials via tf32 mma.sync (HMMA). Grid (64 j-blocks, KSPLIT=7),
// 128 threads (4 warps). Warp w owns j-rows [jb + 16w, jb + 16w + 16).
// Per chunk: stage W[16k x 64j] + x[16k x 32b] (tf32) in smem, then 4 k4-steps
// x 4 n-tiles of m16n8k4. fp32 accumulators.
// ---------------------------------------------------------------------------
__global__ void __launch_bounds__(128) lstm_gemm(
    const float* __restrict__ Wk, const float* __restrict__ Wr)
{
    const int tid  = threadIdx.x;
    const int wid  = tid >> 5, lane = tid & 31;
    const int tig  = lane & 3, grp = lane >> 2;
    const int jb   = blockIdx.x * 64;
    const int ks   = blockIdx.y;
    const int k0   = ks * KPER;

    __shared__ uint32_t ws[CHUNK * WS_STRIDE];   // W chunk, tf32
    __shared__ uint32_t xs[CHUNK * XS_STRIDE];   // x chunk, tf32

    float c0[4], c1[4], c2[4], c3[4];
    #pragma unroll
    for (int nt = 0; nt < 4; nt++) { c0[nt]=0.f; c1[nt]=0.f; c2[nt]=0.f; c3[nt]=0.f; }

    const int woff = wid*16 + grp;               // A-frag j offset within 64

    for (int ch = 0; ch < NCHUNK; ch++) {
        const int kc = k0 + ch*CHUNK;
        __syncthreads();
        // ---- stage W chunk: 16k x 64j = 256 float4, 2 per thread ----
        #pragma unroll
        for (int r = 0; r < 2; r++) {
            int f4 = tid + 128*r;
            int k  = f4 >> 4, jq = f4 & 15;
            int kg = kc + k;
            const float* base = (kg < MELD+ENCD)
                ? (Wk + (long)kg*4096) : (Wr + (long)(kg - MELD - ENCD)*4096);
            float4 v = *((const float4*)(base + jb) + jq);
            uint4 t;
            t.x = cvt_tf32(v.x); t.y = cvt_tf32(v.y);
            t.z = cvt_tf32(v.z); t.w = cvt_tf32(v.w);
            *(uint4*)(ws + k*WS_STRIDE + jq*4) = t;
        }
        // ---- stage x chunk: 16k x 32b = 128 float4, 1 per thread ----
        {
            int k = tid >> 3, b4 = tid & 7;
            float4 v = *((const float4*)(g_xt + (long)(kc + k)*32) + b4);
            uint4 t;
            t.x = cvt_tf32(v.x); t.y = cvt_tf32(v.y);
            t.z = cvt_tf32(v.z); t.w = cvt_tf32(v.w);
            *(uint4*)(xs + k*XS_STRIDE + b4*4) = t;
        }
        __syncthreads();

        // ---- 4 k4-steps ----
        #pragma unroll
        for (int s = 0; s < 4; s++) {
            const int kr = 4*s + tig;
            uint32_t a0 = ws[kr*WS_STRIDE + woff];
            uint32_t a1 = ws[kr*WS_STRIDE + woff + 8];
            #pragma unroll
            for (int nt = 0; nt < 4; nt++) {
                uint32_t b0 = xs[kr*XS_STRIDE + nt*8 + grp];
                mma_tf32(c0[nt], c1[nt], c2[nt], c3[nt], a0, a1, b0);
            }
        }
    }

    // ---- epilogue: standard m16n8 C layout scatter ----
    float* zb = g_zp + (long)(ks*32)*4096 + jb + wid*16;
    #pragma unroll
    for (int nt = 0; nt < 4; nt++) {
        int br = nt*8 + 2*tig;
        zb[(long)(br    )*4096 + grp    ] = c0[nt];
        zb[(long)(br + 1)*4096 + grp    ] = c1[nt];
        zb[(long)(br    )*4096 + grp + 8] = c2[nt];
        zb[(long)(br + 1)*4096 + grp + 8] = c3[nt];
    }
}

// ---------------------------------------------------------------------------
// Kernel D: sum K-split partials + bias, gates. Grid 128 x 256 threads.
// ---------------------------------------------------------------------------
__global__ void __launch_bounds__(256) lstm_gates(
    const float* __restrict__ c_in, const float* __restrict__ bias,
    float* __restrict__ out)
{
    const int idx = blockIdx.x*256 + threadIdx.x;   // [0, 32768)
    const int b = idx >> 10, jj = idx & 1023;

    float zi = bias[jj], zf = bias[DECD + jj];
    float zg = bias[2*DECD + jj], zo = bias[3*DECD + jj];
    #pragma unroll
    for (int ks = 0; ks < KSPLIT; ks++) {
        const float* zp = g_zp + (ks*32 + b)*4*DECD;
        zi += zp[jj];
        zf += zp[DECD + jj];
        zg += zp[2*DECD + jj];
        zo += zp[3*DECD + jj];
    }
    float ig = fast_sig(zi), fg = fast_sig(zf), og = fast_sig(zo);
    float gg = fast_tanh(zg);
    float cn = fmaf(fg, c_in[idx], ig * gg);
    float hn = og * fast_tanh(cn);
    out[OFF_H + idx] = hn;
    out[OFF_C + idx] = cn;
}

// ---------------------------------------------------------------------------
// Kernel E: mel projection. Grid (B), block (96, 4).
// ---------------------------------------------------------------------------
__global__ void __launch_bounds__(384) mel_proj(
    const float* __restrict__ pw, const float* __restrict__ pb,
    float* __restrict__ out)
{
    const int b = blockIdx.x;
    const int j = threadIdx.x;          // 0..95 (80 active)
    const int ty = threadIdx.y;         // 0..3
    __shared__ float red[4][96];

    float a0 = 0.f, a1 = 0.f, a2 = 0.f, a3 = 0.f;
    if (j < MELD) {
        const float* hn = out + OFF_H + b*DECD + ty*256;
        const float* pwk = pw + (long)(ty*256)*MELD + j;
        #pragma unroll 4
        for (int k = 0; k < 256; k += 4) {
            a0 = fmaf(hn[k  ], pwk[(k  )*MELD], a0);
            a1 = fmaf(hn[k+1], pwk[(k+1)*MELD], a1);
            a2 = fmaf(hn[k+2], pwk[(k+2)*MELD], a2);
            a3 = fmaf(hn[k+3], pwk[(k+3)*MELD], a3);
        }
    }
    red[ty][j] = (a0 + a1) + (a2 + a3);
    __syncthreads();
    if (ty == 0 && j < MELD) {
        out[OFF_MEL + b*MELD + j] =
            red[0][j] + red[1][j] + red[2][j] + red[3][j] + pb[j];
    }
}

// ---------------------------------------------------------------------------
extern "C" void kernel_launch(void* const* d_in, const int* in_sizes, int n_in,
                              void* d_out, int out_size)
{
    const float* pm    = (const float*)d_in[0];  // prev_mel_frame [32,80]
    const float* enc   = (const float*)d_in[1];  // encoder_outputs [32,1024,1024]
    const float* h     = (const float*)d_in[2];  // h [32,1024]
    const float* c     = (const float*)d_in[3];  // c [32,1024]
    const float* ascl  = (const float*)d_in[4];  // attn_scale [1024]
    const float* Wk    = (const float*)d_in[5];  // kernel [1104,4096]
    const float* Wr    = (const float*)d_in[6];  // rec_kernel [1024,4096]
    const float* bias  = (const float*)d_in[7];  // bias [4096]
    const float* pw    = (const float*)d_in[8];  // proj_w [1024,80]
    const float* pb    = (const float*)d_in[9];  // proj_b [80]
    float* out = (float*)d_out;

    // Launch 0 (also keeps ncu slot 3 on lstm_gemm): transpose pm/h into g_xt.
    prep_xt<<<266, 256>>>(pm, h);

    dim3 gA(BB, NC);
    attn_partial<<<gA, 256>>>(enc, h, ascl);
    attn_combine<<<BB, 256>>>();
    dim3 gC(64, KSPLIT);
    lstm_gemm<<<gC, 128>>>(Wk, Wr);
    lstm_gates<<<128, 256>>>(c, bias, out);
    dim3 bE(96, 4);
    mel_proj<<<BB, bE>>>(pw, pb, out);
}